// round 6
// baseline (speedup 1.0000x reference)
#include <cuda_runtime.h>
#include <math.h>

#define D 64
#define TWOD 128
#define RD 256            // RANK*D
#define W1SREF 68         // padded stride for W1 rows (68 % 32 == 4 -> conflict free both ways)
#define W2SREF 132        // padded stride for W2 rows
#define WARPS 8
#define THREADS (WARPS * 32)
#define SCR_PER_WARP 896  // 64+64+128+256+256+128

// dynamic smem floats: W1s(128*68) + W2s(256*132) + b1(128) + b2(256) + 8*896
#define SMEM_FLOATS (TWOD*W1SREF + RD*W2SREF + TWOD + RD + WARPS*SCR_PER_WARP)

__device__ __forceinline__ float my_tanh(float x) {
    float xc = fminf(fmaxf(x, -10.0f), 10.0f);
    float e = __expf(2.0f * xc);
    return __fdividef(e - 1.0f, e + 1.0f);
}

__global__ __launch_bounds__(THREADS, 1)
void geognn_grad_kernel(const float* __restrict__ input,
                        const float* __restrict__ W1, const float* __restrict__ b1,
                        const float* __restrict__ W2, const float* __restrict__ b2,
                        float* __restrict__ out, int n)
{
    extern __shared__ float smem[];
    float* W1s = smem;                      // [128][68]
    float* W2s = W1s + TWOD * W1SREF;       // [256][132]
    float* b1s = W2s + RD * W2SREF;         // [128]
    float* b2s = b1s + TWOD;                // [256]
    float* scr = b2s + RD;

    const int tid = threadIdx.x;
    const int w   = tid >> 5;
    const int l   = tid & 31;

    // ---- cooperative weight staging (vectorized) ----
    {
        const float4* W1v = (const float4*)W1;   // 128*16 float4
        for (int i = tid; i < TWOD * (D / 4); i += THREADS) {
            int j = i >> 4, k4 = i & 15;
            *(float4*)(W1s + j * W1SREF + 4 * k4) = W1v[i];
        }
        const float4* W2v = (const float4*)W2;   // 256*32 float4
        for (int i = tid; i < RD * (TWOD / 4); i += THREADS) {
            int j = i >> 5, k4 = i & 31;
            *(float4*)(W2s + j * W2SREF + 4 * k4) = W2v[i];
        }
        for (int i = tid; i < TWOD; i += THREADS) b1s[i] = b1[i];
        for (int i = tid; i < RD;   i += THREADS) b2s[i] = b2[i];
    }
    __syncthreads();

    float* xs  = scr + w * SCR_PER_WARP;  // 64
    float* vs  = xs + 64;                 // 64
    float* hs  = vs + 64;                 // 128
    float* wms = hs + 128;                // 256
    float* gs  = wms + 256;               // 256
    float* dus = gs + 256;                // 128

    const int gw = blockIdx.x * WARPS + w;
    const int nw = gridDim.x * WARPS;

    for (int row = gw; row < n; row += nw) {
        __syncwarp();  // serialize iterations (protects scratch reuse)

        const float* inrow  = input + (size_t)row * TWOD;
        float*       outrow = out   + (size_t)row * TWOD;

        // ---- load x|v (128 floats, 1 float4 per lane) ----
        ((float4*)xs)[l] = ((const float4*)inrow)[l];
        __syncwarp();

        // ---- u = W1 @ x + b1 ; h = tanh(u)  (lane handles j = l, l+32, l+64, l+96)
        float a0 = b1s[l], a1 = b1s[l + 32], a2 = b1s[l + 64], a3 = b1s[l + 96];
        {
            const float* p0 = W1s + (l)      * W1SREF;
            const float* p1 = W1s + (l + 32) * W1SREF;
            const float* p2 = W1s + (l + 64) * W1SREF;
            const float* p3 = W1s + (l + 96) * W1SREF;
            #pragma unroll
            for (int k = 0; k < D; k += 4) {
                float4 xk = *(const float4*)(xs + k);
                float4 q0 = *(const float4*)(p0 + k);
                float4 q1 = *(const float4*)(p1 + k);
                float4 q2 = *(const float4*)(p2 + k);
                float4 q3 = *(const float4*)(p3 + k);
                a0 = fmaf(q0.x, xk.x, a0); a0 = fmaf(q0.y, xk.y, a0);
                a0 = fmaf(q0.z, xk.z, a0); a0 = fmaf(q0.w, xk.w, a0);
                a1 = fmaf(q1.x, xk.x, a1); a1 = fmaf(q1.y, xk.y, a1);
                a1 = fmaf(q1.z, xk.z, a1); a1 = fmaf(q1.w, xk.w, a1);
                a2 = fmaf(q2.x, xk.x, a2); a2 = fmaf(q2.y, xk.y, a2);
                a2 = fmaf(q2.z, xk.z, a2); a2 = fmaf(q2.w, xk.w, a2);
                a3 = fmaf(q3.x, xk.x, a3); a3 = fmaf(q3.y, xk.y, a3);
                a3 = fmaf(q3.z, xk.z, a3); a3 = fmaf(q3.w, xk.w, a3);
            }
        }
        float h0 = my_tanh(a0), h1 = my_tanh(a1), h2 = my_tanh(a2), h3 = my_tanh(a3);
        hs[l] = h0; hs[l + 32] = h1; hs[l + 64] = h2; hs[l + 96] = h3;
        __syncwarp();

        // ---- m = W2 @ h + b2 ; wm = tanh(m)  (lane handles j = l + 32t, t=0..7)
        float mac[8];
        #pragma unroll
        for (int t = 0; t < 8; t++) mac[t] = b2s[l + 32 * t];
        #pragma unroll 2
        for (int k = 0; k < TWOD; k += 4) {
            float4 hk = *(const float4*)(hs + k);
            #pragma unroll
            for (int t = 0; t < 8; t++) {
                float4 q = *(const float4*)(W2s + (l + 32 * t) * W2SREF + k);
                mac[t] = fmaf(q.x, hk.x, mac[t]); mac[t] = fmaf(q.y, hk.y, mac[t]);
                mac[t] = fmaf(q.z, hk.z, mac[t]); mac[t] = fmaf(q.w, hk.w, mac[t]);
            }
        }
        float wmv[8];
        #pragma unroll
        for (int t = 0; t < 8; t++) { wmv[t] = my_tanh(mac[t]); wms[l + 32 * t] = wmv[t]; }

        // v values matching this lane's wm entries: j=l+32t -> i=(l>>2)+8t, r=l&3
        float vi[8];
        #pragma unroll
        for (int t = 0; t < 8; t++) vi[t] = vs[(l >> 2) + 8 * t];

        // ---- y[r] = sum_i v[i]*Wm[i][r]  (reduce across the 8 lanes sharing r=l&3)
        float yacc = 0.f;
        #pragma unroll
        for (int t = 0; t < 8; t++) yacc = fmaf(vi[t], wmv[t], yacc);
        yacc += __shfl_xor_sync(0xffffffffu, yacc, 4);
        yacc += __shfl_xor_sync(0xffffffffu, yacc, 8);
        yacc += __shfl_xor_sync(0xffffffffu, yacc, 16);
        const float yr = yacc;                               // = y[l&3]
        const float y0 = __shfl_sync(0xffffffffu, yacc, 0);
        const float y1 = __shfl_sync(0xffffffffu, yacc, 1);
        const float y2 = __shfl_sync(0xffffffffu, yacc, 2);
        const float y3 = __shfl_sync(0xffffffffu, yacc, 3);

        // ---- g[j] = 2*y[r]*v[i]*(1 - wm^2)
        #pragma unroll
        for (int t = 0; t < 8; t++) {
            gs[l + 32 * t] = 2.0f * yr * vi[t] * (1.0f - wmv[t] * wmv[t]);
        }
        __syncwarp();

        // ---- dv[i] = 2 * sum_r y[r]*Wm[i][r]  -> out[64+i] = -dv[i]
        #pragma unroll
        for (int t = 0; t < 2; t++) {
            int i = l + 32 * t;
            float4 wq = *(const float4*)(wms + 4 * i);
            float dvv = fmaf(y0, wq.x, fmaf(y1, wq.y, fmaf(y2, wq.z, y3 * wq.w)));
            outrow[D + i] = -2.0f * dvv;
        }

        // ---- dh[k] = sum_j W2[j][k]*g[j] ; du = dh*(1-h^2)  (lane handles k = 4l..4l+3)
        float d0 = 0.f, d1 = 0.f, d2 = 0.f, d3 = 0.f;
        {
            const float* c = W2s + 4 * l;
            #pragma unroll 2
            for (int j = 0; j < RD; j += 4) {
                float4 gj = *(const float4*)(gs + j);
                float4 r0 = *(const float4*)(c + (j)     * W2SREF);
                float4 r1 = *(const float4*)(c + (j + 1) * W2SREF);
                float4 r2 = *(const float4*)(c + (j + 2) * W2SREF);
                float4 r3 = *(const float4*)(c + (j + 3) * W2SREF);
                d0 = fmaf(gj.x, r0.x, d0); d0 = fmaf(gj.y, r1.x, d0);
                d0 = fmaf(gj.z, r2.x, d0); d0 = fmaf(gj.w, r3.x, d0);
                d1 = fmaf(gj.x, r0.y, d1); d1 = fmaf(gj.y, r1.y, d1);
                d1 = fmaf(gj.z, r2.y, d1); d1 = fmaf(gj.w, r3.y, d1);
                d2 = fmaf(gj.x, r0.z, d2); d2 = fmaf(gj.y, r1.z, d2);
                d2 = fmaf(gj.z, r2.z, d2); d2 = fmaf(gj.w, r3.z, d2);
                d3 = fmaf(gj.x, r0.w, d3); d3 = fmaf(gj.y, r1.w, d3);
                d3 = fmaf(gj.z, r2.w, d3); d3 = fmaf(gj.w, r3.w, d3);
            }
        }
        {
            float4 hk = *(const float4*)(hs + 4 * l);
            float4 du;
            du.x = d0 * (1.0f - hk.x * hk.x);
            du.y = d1 * (1.0f - hk.y * hk.y);
            du.z = d2 * (1.0f - hk.z * hk.z);
            du.w = d3 * (1.0f - hk.w * hk.w);
            *(float4*)(dus + 4 * l) = du;
        }
        __syncwarp();

        // ---- dx[i] = sum_j W1[j][i]*du[j]  (lane handles i = 2l, 2l+1)
        float x0 = 0.f, x1 = 0.f;
        {
            const float* c = W1s + 2 * l;
            #pragma unroll 2
            for (int j = 0; j < TWOD; j += 4) {
                float4 dj = *(const float4*)(dus + j);
                float2 c0 = *(const float2*)(c + (j)     * W1SREF);
                float2 c1 = *(const float2*)(c + (j + 1) * W1SREF);
                float2 c2 = *(const float2*)(c + (j + 2) * W1SREF);
                float2 c3 = *(const float2*)(c + (j + 3) * W1SREF);
                x0 = fmaf(dj.x, c0.x, x0); x0 = fmaf(dj.y, c1.x, x0);
                x0 = fmaf(dj.z, c2.x, x0); x0 = fmaf(dj.w, c3.x, x0);
                x1 = fmaf(dj.x, c0.y, x1); x1 = fmaf(dj.y, c1.y, x1);
                x1 = fmaf(dj.z, c2.y, x1); x1 = fmaf(dj.w, c3.y, x1);
            }
        }
        *(float2*)(outrow + 2 * l) = make_float2(x0, x1);
    }
}

extern "C" void kernel_launch(void* const* d_in, const int* in_sizes, int n_in,
                              void* d_out, int out_size) {
    // inputs: t(1), input_(N*128), W1(128*64), b1(128), W2(256*128), b2(256)
    const float* input = (const float*)d_in[1];
    const float* W1    = (const float*)d_in[2];
    const float* b1    = (const float*)d_in[3];
    const float* W2    = (const float*)d_in[4];
    const float* b2    = (const float*)d_in[5];
    float* out = (float*)d_out;
    const int n = in_sizes[1] / TWOD;

    static_assert(SMEM_FLOATS * 4 < 232448, "smem budget");

    int dev = 0;
    cudaGetDevice(&dev);
    int nsm = 148;
    cudaDeviceGetAttribute(&nsm, cudaDevAttrMultiProcessorCount, dev);

    cudaFuncSetAttribute(geognn_grad_kernel,
                         cudaFuncAttributeMaxDynamicSharedMemorySize,
                         SMEM_FLOATS * (int)sizeof(float));

    geognn_grad_kernel<<<nsm, THREADS, SMEM_FLOATS * (int)sizeof(float)>>>(
        input, W1, b1, W2, b2, out, n);
}

// round 7
// speedup vs baseline: 2.1711x; 2.1711x over previous
#include <cuda_runtime.h>
#include <math.h>

#define D 64
#define TWOD 128
#define RD 256            // RANK*D
#define W1S 68            // padded stride for W1 rows
#define W2S 132           // padded stride for W2 rows
#define WARPS 8
#define RB 3              // rows per warp (register blocking)
#define THREADS (WARPS * 32)
#define SLOT 512          // per-row scratch floats: xv(128, reused as du) + hs(128) + gs(256)

// dynamic smem floats
#define SMEM_FLOATS (TWOD*W1S + RD*W2S + TWOD + RD + WARPS*RB*SLOT)

__device__ __forceinline__ float my_tanh(float x) {
    float xc = fminf(fmaxf(x, -10.0f), 10.0f);
    float e = __expf(2.0f * xc);
    return __fdividef(e - 1.0f, e + 1.0f);
}

__global__ __launch_bounds__(THREADS, 1)
void geognn_grad_kernel(const float* __restrict__ input,
                        const float* __restrict__ W1, const float* __restrict__ b1,
                        const float* __restrict__ W2, const float* __restrict__ b2,
                        float* __restrict__ out, int n)
{
    extern __shared__ float smem[];
    float* W1s = smem;                      // [128][68]
    float* W2s = W1s + TWOD * W1S;          // [256][132]
    float* b1s = W2s + RD * W2S;            // [128]
    float* b2s = b1s + TWOD;                // [256]
    float* scr = b2s + RD;

    const int tid = threadIdx.x;
    const int w   = tid >> 5;
    const int l   = tid & 31;

    // ---- cooperative weight staging (vectorized) ----
    {
        const float4* W1v = (const float4*)W1;   // 128*16 float4
        for (int i = tid; i < TWOD * (D / 4); i += THREADS) {
            int j = i >> 4, k4 = i & 15;
            *(float4*)(W1s + j * W1S + 4 * k4) = W1v[i];
        }
        const float4* W2v = (const float4*)W2;   // 256*32 float4
        for (int i = tid; i < RD * (TWOD / 4); i += THREADS) {
            int j = i >> 5, k4 = i & 31;
            *(float4*)(W2s + j * W2S + 4 * k4) = W2v[i];
        }
        for (int i = tid; i < TWOD; i += THREADS) b1s[i] = b1[i];
        for (int i = tid; i < RD;   i += THREADS) b2s[i] = b2[i];
    }
    __syncthreads();

    // per-row scratch slots
    float* xv[RB];  // x|v (128); later overlaid with du
    float* hs[RB];  // h (128)
    float* gs[RB];  // g (256)
    #pragma unroll
    for (int r = 0; r < RB; r++) {
        float* s = scr + (w * RB + r) * SLOT;
        xv[r] = s; hs[r] = s + 128; gs[r] = s + 256;
    }

    const int gw = blockIdx.x * WARPS + w;
    const int nw = gridDim.x * WARPS;

    for (long base = (long)gw * RB; base < n; base += (long)nw * RB) {
        __syncwarp();   // protect scratch reuse across iterations

        int rows[RB];
        #pragma unroll
        for (int r = 0; r < RB; r++) {
            int rr = (int)base + r;
            rows[r] = rr < n ? rr : (n - 1);   // clamp: duplicate work, identical stores
        }

        // ---- load x|v ----
        #pragma unroll
        for (int r = 0; r < RB; r++)
            ((float4*)xv[r])[l] = ((const float4*)(input + (size_t)rows[r] * TWOD))[l];
        __syncwarp();

        // ==== forward layer 1: u = W1 @ x + b1 ; h = tanh(u) ====
        // lane handles outputs j = l, l+32, l+64, l+96, for all RB rows
        float a[RB][4];
        #pragma unroll
        for (int r = 0; r < RB; r++)
            #pragma unroll
            for (int p = 0; p < 4; p++) a[r][p] = b1s[l + 32 * p];

        #pragma unroll 4
        for (int k = 0; k < D; k += 4) {
            float4 q0 = *(const float4*)(W1s + (l)      * W1S + k);
            float4 q1 = *(const float4*)(W1s + (l + 32) * W1S + k);
            float4 q2 = *(const float4*)(W1s + (l + 64) * W1S + k);
            float4 q3 = *(const float4*)(W1s + (l + 96) * W1S + k);
            #pragma unroll
            for (int r = 0; r < RB; r++) {
                float4 xk = *(const float4*)(xv[r] + k);
                a[r][0] = fmaf(q0.x, xk.x, a[r][0]); a[r][0] = fmaf(q0.y, xk.y, a[r][0]);
                a[r][0] = fmaf(q0.z, xk.z, a[r][0]); a[r][0] = fmaf(q0.w, xk.w, a[r][0]);
                a[r][1] = fmaf(q1.x, xk.x, a[r][1]); a[r][1] = fmaf(q1.y, xk.y, a[r][1]);
                a[r][1] = fmaf(q1.z, xk.z, a[r][1]); a[r][1] = fmaf(q1.w, xk.w, a[r][1]);
                a[r][2] = fmaf(q2.x, xk.x, a[r][2]); a[r][2] = fmaf(q2.y, xk.y, a[r][2]);
                a[r][2] = fmaf(q2.z, xk.z, a[r][2]); a[r][2] = fmaf(q2.w, xk.w, a[r][2]);
                a[r][3] = fmaf(q3.x, xk.x, a[r][3]); a[r][3] = fmaf(q3.y, xk.y, a[r][3]);
                a[r][3] = fmaf(q3.z, xk.z, a[r][3]); a[r][3] = fmaf(q3.w, xk.w, a[r][3]);
            }
        }
        #pragma unroll
        for (int r = 0; r < RB; r++) {
            hs[r][l]      = my_tanh(a[r][0]);
            hs[r][l + 32] = my_tanh(a[r][1]);
            hs[r][l + 64] = my_tanh(a[r][2]);
            hs[r][l + 96] = my_tanh(a[r][3]);
        }
        __syncwarp();

        // ==== forward layer 2: m = W2 @ h + b2  (lane handles j = l + 32t) ====
        float mac[8][RB];
        #pragma unroll
        for (int t = 0; t < 8; t++)
            #pragma unroll
            for (int r = 0; r < RB; r++) mac[t][r] = b2s[l + 32 * t];

        #pragma unroll 2
        for (int k = 0; k < TWOD; k += 4) {
            float4 hk[RB];
            #pragma unroll
            for (int r = 0; r < RB; r++) hk[r] = *(const float4*)(hs[r] + k);
            #pragma unroll
            for (int t = 0; t < 8; t++) {
                float4 q = *(const float4*)(W2s + (l + 32 * t) * W2S + k);
                #pragma unroll
                for (int r = 0; r < RB; r++) {
                    mac[t][r] = fmaf(q.x, hk[r].x, mac[t][r]);
                    mac[t][r] = fmaf(q.y, hk[r].y, mac[t][r]);
                    mac[t][r] = fmaf(q.z, hk[r].z, mac[t][r]);
                    mac[t][r] = fmaf(q.w, hk[r].w, mac[t][r]);
                }
            }
        }

        // ==== middle: wm = tanh(m); y; g; dv (per row, wm register-resident) ====
        // lane's j = l+32t maps to Wm[i][rcol] with i=(l>>2)+8t, rcol=l&3
        #pragma unroll
        for (int r = 0; r < RB; r++) {
            float wm[8], vi[8];
            #pragma unroll
            for (int t = 0; t < 8; t++) wm[t] = my_tanh(mac[t][r]);
            #pragma unroll
            for (int t = 0; t < 8; t++) vi[t] = xv[r][64 + (l >> 2) + 8 * t];

            float y = 0.f;
            #pragma unroll
            for (int t = 0; t < 8; t++) y = fmaf(vi[t], wm[t], y);
            y += __shfl_xor_sync(0xffffffffu, y, 4);
            y += __shfl_xor_sync(0xffffffffu, y, 8);
            y += __shfl_xor_sync(0xffffffffu, y, 16);  // y = y[l&3] on every lane

            float* outrow = out + (size_t)rows[r] * TWOD;
            #pragma unroll
            for (int t = 0; t < 8; t++) {
                // dv[i] = 2 * sum_r y[r]*Wm[i][r] via quad reduction
                float p = y * wm[t];
                p += __shfl_xor_sync(0xffffffffu, p, 1);
                p += __shfl_xor_sync(0xffffffffu, p, 2);
                if ((l & 3) == 0) outrow[D + (l >> 2) + 8 * t] = -2.0f * p;
                // g[j] = 2*y*v[i]*(1 - wm^2)
                gs[r][l + 32 * t] = 2.0f * y * vi[t] * (1.0f - wm[t] * wm[t]);
            }
        }
        __syncwarp();

        // ==== backward: dh[k] = sum_j W2[j][k]*g[j] ; du = dh*(1-h^2) ====
        // lane handles columns k = 4l..4l+3
        float dacc[RB][4];
        #pragma unroll
        for (int r = 0; r < RB; r++)
            #pragma unroll
            for (int p = 0; p < 4; p++) dacc[r][p] = 0.f;

        {
            const float* c2 = W2s + 4 * l;
            #pragma unroll 2
            for (int j = 0; j < RD; j += 4) {
                float4 r0 = *(const float4*)(c2 + (j)     * W2S);
                float4 r1 = *(const float4*)(c2 + (j + 1) * W2S);
                float4 r2 = *(const float4*)(c2 + (j + 2) * W2S);
                float4 r3 = *(const float4*)(c2 + (j + 3) * W2S);
                #pragma unroll
                for (int r = 0; r < RB; r++) {
                    float4 gj = *(const float4*)(gs[r] + j);
                    dacc[r][0] = fmaf(gj.x, r0.x, dacc[r][0]); dacc[r][0] = fmaf(gj.y, r1.x, dacc[r][0]);
                    dacc[r][0] = fmaf(gj.z, r2.x, dacc[r][0]); dacc[r][0] = fmaf(gj.w, r3.x, dacc[r][0]);
                    dacc[r][1] = fmaf(gj.x, r0.y, dacc[r][1]); dacc[r][1] = fmaf(gj.y, r1.y, dacc[r][1]);
                    dacc[r][1] = fmaf(gj.z, r2.y, dacc[r][1]); dacc[r][1] = fmaf(gj.w, r3.y, dacc[r][1]);
                    dacc[r][2] = fmaf(gj.x, r0.z, dacc[r][2]); dacc[r][2] = fmaf(gj.y, r1.z, dacc[r][2]);
                    dacc[r][2] = fmaf(gj.z, r2.z, dacc[r][2]); dacc[r][2] = fmaf(gj.w, r3.z, dacc[r][2]);
                    dacc[r][3] = fmaf(gj.x, r0.w, dacc[r][3]); dacc[r][3] = fmaf(gj.y, r1.w, dacc[r][3]);
                    dacc[r][3] = fmaf(gj.z, r2.w, dacc[r][3]); dacc[r][3] = fmaf(gj.w, r3.w, dacc[r][3]);
                }
            }
        }
        // du = dh * (1-h^2), overlay onto xv (x|v dead now)
        #pragma unroll
        for (int r = 0; r < RB; r++) {
            float4 hk = *(const float4*)(hs[r] + 4 * l);
            float4 du;
            du.x = dacc[r][0] * (1.0f - hk.x * hk.x);
            du.y = dacc[r][1] * (1.0f - hk.y * hk.y);
            du.z = dacc[r][2] * (1.0f - hk.z * hk.z);
            du.w = dacc[r][3] * (1.0f - hk.w * hk.w);
            *(float4*)(xv[r] + 4 * l) = du;
        }
        __syncwarp();

        // ==== backward: dx[i] = sum_j W1[j][i]*du[j]  (lane handles i = 2l, 2l+1) ====
        float xo[RB][2];
        #pragma unroll
        for (int r = 0; r < RB; r++) { xo[r][0] = 0.f; xo[r][1] = 0.f; }
        {
            const float* c1 = W1s + 2 * l;
            #pragma unroll 2
            for (int j = 0; j < TWOD; j += 4) {
                float2 c0 = *(const float2*)(c1 + (j)     * W1S);
                float2 ca = *(const float2*)(c1 + (j + 1) * W1S);
                float2 cb = *(const float2*)(c1 + (j + 2) * W1S);
                float2 cc = *(const float2*)(c1 + (j + 3) * W1S);
                #pragma unroll
                for (int r = 0; r < RB; r++) {
                    float4 dj = *(const float4*)(xv[r] + j);
                    xo[r][0] = fmaf(dj.x, c0.x, xo[r][0]); xo[r][0] = fmaf(dj.y, ca.x, xo[r][0]);
                    xo[r][0] = fmaf(dj.z, cb.x, xo[r][0]); xo[r][0] = fmaf(dj.w, cc.x, xo[r][0]);
                    xo[r][1] = fmaf(dj.x, c0.y, xo[r][1]); xo[r][1] = fmaf(dj.y, ca.y, xo[r][1]);
                    xo[r][1] = fmaf(dj.z, cb.y, xo[r][1]); xo[r][1] = fmaf(dj.w, cc.y, xo[r][1]);
                }
            }
        }
        #pragma unroll
        for (int r = 0; r < RB; r++)
            *(float2*)(out + (size_t)rows[r] * TWOD + 2 * l) = make_float2(xo[r][0], xo[r][1]);
    }
}

extern "C" void kernel_launch(void* const* d_in, const int* in_sizes, int n_in,
                              void* d_out, int out_size) {
    // inputs: t(1), input_(N*128), W1(128*64), b1(128), W2(256*128), b2(256)
    const float* input = (const float*)d_in[1];
    const float* W1    = (const float*)d_in[2];
    const float* b1    = (const float*)d_in[3];
    const float* W2    = (const float*)d_in[4];
    const float* b2    = (const float*)d_in[5];
    float* out = (float*)d_out;
    const int n = in_sizes[1] / TWOD;

    static_assert(SMEM_FLOATS * 4 < 232448, "smem budget");

    int dev = 0;
    cudaGetDevice(&dev);
    int nsm = 148;
    cudaDeviceGetAttribute(&nsm, cudaDevAttrMultiProcessorCount, dev);

    cudaFuncSetAttribute(geognn_grad_kernel,
                         cudaFuncAttributeMaxDynamicSharedMemorySize,
                         SMEM_FLOATS * (int)sizeof(float));

    geognn_grad_kernel<<<nsm, THREADS, SMEM_FLOATS * (int)sizeof(float)>>>(
        input, W1, b1, W2, b2, out, n);
}